// round 1
// baseline (speedup 1.0000x reference)
#include <cuda_runtime.h>
#include <math.h>
#include <stdint.h>

#define NNODES 65536
#define NEDGES 262144
#define NBATCH 2048
#define FIN    78
#define GOUTD  512
#define NHEADS 8
#define HIDD   64
#define NSELF  (NEDGES + NNODES)

// ---------------- scratch (device globals; no allocation allowed) ----------
__device__ float g_h1[(size_t)NNODES * GOUTD];   // GEMM output (messages)
__device__ float g_h2[(size_t)NNODES * GOUTD];   // aggregation output / next input
__device__ float g_asrc[NNODES * NHEADS];
__device__ float g_adst[NNODES * NHEADS];
__device__ float g_emax[NNODES * NHEADS];
__device__ float g_denom[NNODES * NHEADS];
__device__ float g_psum[NBATCH * GOUTD];
__device__ float g_cnt[NBATCH];
__device__ float g_z1[NBATCH * 128];
__device__ float g_z2[NBATCH * GOUTD];
__device__ float g_cbuf[NBATCH * 1024];
__device__ float g_f1[NBATCH * 256];
__device__ float g_f2[NBATCH * 128];

// ---------------- utility ----------------
__global__ void fill_kernel(float* p, int n, float v) {
    int i = blockIdx.x * blockDim.x + threadIdx.x;
    if (i < n) p[i] = v;
}

__device__ __forceinline__ void atomicMaxFloat(float* addr, float v) {
    // standard monotone-bits trick: int-max for v>=0, uint-min for v<0.
    if (v >= 0.f) atomicMax((int*)addr, __float_as_int(v));
    else          atomicMin((unsigned int*)addr, __float_as_uint(v));
}

// ---------------- generic tiled SGEMM with fused epilogue ----------------
// C[M,N] = A[M,K] @ B[K,N]; epi: 0=none, 1=+bias, 2=+bias,relu, 3=+bias,BN,relu
#define TM 64
#define TN 64
#define TK 16
__global__ void sgemm_kernel(const float* __restrict__ A, const float* __restrict__ B,
                             float* __restrict__ C, int M, int N, int K,
                             const float* __restrict__ bias, int epi,
                             const float* __restrict__ bn_gamma, const float* __restrict__ bn_beta,
                             const float* __restrict__ bn_mean, const float* __restrict__ bn_var) {
    __shared__ float As[TK][TM + 1];
    __shared__ float Bs[TK][TN];

    int tx = threadIdx.x, ty = threadIdx.y;
    int tid = ty * 16 + tx;
    int row0 = blockIdx.y * TM;
    int col0 = blockIdx.x * TN;

    float acc[4][4];
#pragma unroll
    for (int i = 0; i < 4; i++)
#pragma unroll
        for (int j = 0; j < 4; j++) acc[i][j] = 0.f;

    for (int k0 = 0; k0 < K; k0 += TK) {
        // load A tile (TM x TK) -> As[k][m]
#pragma unroll
        for (int i = tid; i < TM * TK; i += 256) {
            int m = i / TK, k = i % TK;
            int gm = row0 + m, gk = k0 + k;
            float v = 0.f;
            if (gm < M && gk < K) v = A[(size_t)gm * K + gk];
            As[k][m] = v;
        }
        // load B tile (TK x TN) -> Bs[k][n]
#pragma unroll
        for (int i = tid; i < TK * TN; i += 256) {
            int k = i / TN, n = i % TN;
            int gk = k0 + k, gn = col0 + n;
            float v = 0.f;
            if (gk < K && gn < N) v = B[(size_t)gk * N + gn];
            Bs[k][n] = v;
        }
        __syncthreads();
#pragma unroll
        for (int kk = 0; kk < TK; kk++) {
            float a[4];
#pragma unroll
            for (int i = 0; i < 4; i++) a[i] = As[kk][ty * 4 + i];
            float4 bv = *reinterpret_cast<const float4*>(&Bs[kk][tx * 4]);
            float b[4] = {bv.x, bv.y, bv.z, bv.w};
#pragma unroll
            for (int i = 0; i < 4; i++)
#pragma unroll
                for (int j = 0; j < 4; j++) acc[i][j] = fmaf(a[i], b[j], acc[i][j]);
        }
        __syncthreads();
    }

#pragma unroll
    for (int i = 0; i < 4; i++) {
        int gm = row0 + ty * 4 + i;
        if (gm >= M) continue;
#pragma unroll
        for (int j = 0; j < 4; j++) {
            int gn = col0 + tx * 4 + j;
            if (gn >= N) continue;
            float v = acc[i][j];
            if (epi >= 1) v += bias[gn];
            if (epi == 3) {
                float sc = bn_gamma[gn] * rsqrtf(bn_var[gn] + 1e-5f);
                v = (v - bn_mean[gn]) * sc + bn_beta[gn];
            }
            if (epi >= 2) v = fmaxf(v, 0.f);
            C[(size_t)gm * N + gn] = v;
        }
    }
}

// ---------------- GAT pieces ----------------
// a_src[n,h] = dot(h[n, h*64 : h*64+64], att_src[h]); similarly a_dst.
__global__ void attn_coef_kernel(const float* __restrict__ h,
                                 const float* __restrict__ att_src,
                                 const float* __restrict__ att_dst,
                                 float* __restrict__ a_src, float* __restrict__ a_dst) {
    int idx = blockIdx.x * blockDim.x + threadIdx.x;
    if (idx >= NNODES * NHEADS) return;
    int n = idx >> 3, hd = idx & 7;
    const float* hp = h + (size_t)n * GOUTD + hd * HIDD;
    const float* as = att_src + hd * HIDD;
    const float* ad = att_dst + hd * HIDD;
    float s = 0.f, d = 0.f;
#pragma unroll 8
    for (int c = 0; c < HIDD; c++) {
        float v = hp[c];
        s = fmaf(v, as[c], s);
        d = fmaf(v, ad[c], d);
    }
    a_src[idx] = s;
    a_dst[idx] = d;
}

__device__ __forceinline__ void edge_nodes(const int* ei, int e, int& s, int& d) {
    if (e < NEDGES) { s = ei[e]; d = ei[NEDGES + e]; }
    else            { s = e - NEDGES; d = s; }
}

__global__ void edge_max_kernel(const int* __restrict__ ei,
                                const float* __restrict__ a_src, const float* __restrict__ a_dst,
                                float* __restrict__ emax) {
    int idx = blockIdx.x * blockDim.x + threadIdx.x;
    if (idx >= NSELF * NHEADS) return;
    int e = idx >> 3, hd = idx & 7;
    int s, d; edge_nodes(ei, e, s, d);
    float v = a_src[s * NHEADS + hd] + a_dst[d * NHEADS + hd];
    v = v > 0.f ? v : 0.2f * v;
    atomicMaxFloat(&emax[d * NHEADS + hd], v);
}

__global__ void edge_denom_kernel(const int* __restrict__ ei,
                                  const float* __restrict__ a_src, const float* __restrict__ a_dst,
                                  const float* __restrict__ emax, float* __restrict__ denom) {
    int idx = blockIdx.x * blockDim.x + threadIdx.x;
    if (idx >= NSELF * NHEADS) return;
    int e = idx >> 3, hd = idx & 7;
    int s, d; edge_nodes(ei, e, s, d);
    float v = a_src[s * NHEADS + hd] + a_dst[d * NHEADS + hd];
    v = v > 0.f ? v : 0.2f * v;
    atomicAdd(&denom[d * NHEADS + hd], expf(v - emax[d * NHEADS + hd]));
}

// block per edge: 512 threads, 8 heads * 64 channels; alpha in smem
__global__ void edge_agg_kernel(const int* __restrict__ ei,
                                const float* __restrict__ a_src, const float* __restrict__ a_dst,
                                const float* __restrict__ emax, const float* __restrict__ denom,
                                const float* __restrict__ h, float* __restrict__ out) {
    __shared__ float alpha[NHEADS];
    __shared__ int snode, dnode;
    int e = blockIdx.x;
    int t = threadIdx.x;
    if (t == 0) {
        int s, d; edge_nodes(ei, e, s, d);
        snode = s; dnode = d;
    }
    __syncthreads();
    int s = snode, d = dnode;
    if (t < NHEADS) {
        float v = a_src[s * NHEADS + t] + a_dst[d * NHEADS + t];
        v = v > 0.f ? v : 0.2f * v;
        alpha[t] = expf(v - emax[d * NHEADS + t]) / (denom[d * NHEADS + t] + 1e-16f);
    }
    __syncthreads();
    int hd = t >> 6;
    float msg = h[(size_t)s * GOUTD + t] * alpha[hd];
    atomicAdd(&out[(size_t)d * GOUTD + t], msg);
}

__global__ void bias_elu_kernel(float* __restrict__ buf, const float* __restrict__ bias) {
    size_t idx = (size_t)blockIdx.x * blockDim.x + threadIdx.x;
    if (idx >= (size_t)NNODES * GOUTD) return;
    int c = idx & (GOUTD - 1);
    float v = buf[idx] + bias[c];
    buf[idx] = v > 0.f ? v : (expf(v) - 1.f);
}

// ---------------- pooling / concat / final ----------------
__global__ void pool_kernel(const float* __restrict__ h, const int* __restrict__ batch,
                            float* __restrict__ psum, float* __restrict__ cnt) {
    size_t idx = (size_t)blockIdx.x * blockDim.x + threadIdx.x;
    if (idx >= (size_t)NNODES * GOUTD) return;
    int n = (int)(idx >> 9);
    int c = (int)(idx & (GOUTD - 1));
    int b = batch[n];
    atomicAdd(&psum[b * GOUTD + c], h[idx]);
    if (c == 0) atomicAdd(&cnt[b], 1.f);
}

__global__ void concat_kernel(const float* __restrict__ psum, const float* __restrict__ cnt,
                              const float* __restrict__ z2, float* __restrict__ cbuf) {
    int idx = blockIdx.x * blockDim.x + threadIdx.x;
    if (idx >= NBATCH * GOUTD) return;
    int b = idx >> 9, c = idx & (GOUTD - 1);
    float cv = cnt[b];
    cv = cv < 1.f ? 1.f : cv;
    cbuf[b * 1024 + c]       = psum[idx] / cv;
    cbuf[b * 1024 + 512 + c] = z2[idx];
}

// out[m] = dot(f2[m,0:128], w) + b;  warp per row
__global__ void final_dot_kernel(const float* __restrict__ f2, const float* __restrict__ w,
                                 const float* __restrict__ b, float* __restrict__ out) {
    int row = blockIdx.x;
    int lane = threadIdx.x;
    float s = 0.f;
    for (int c = lane; c < 128; c += 32) s = fmaf(f2[row * 128 + c], w[c], s);
#pragma unroll
    for (int off = 16; off > 0; off >>= 1) s += __shfl_xor_sync(0xFFFFFFFFu, s, off);
    if (lane == 0) out[row] = s + b[0];
}

// ---------------- host-side orchestration ----------------
static inline void launch_fill(float* p, int n, float v) {
    fill_kernel<<<(n + 255) / 256, 256>>>(p, n, v);
}

static inline void launch_sgemm(const float* A, const float* B, float* C, int M, int N, int K,
                                const float* bias, int epi,
                                const float* g = nullptr, const float* be = nullptr,
                                const float* mn = nullptr, const float* vr = nullptr) {
    dim3 grid((N + TN - 1) / TN, (M + TM - 1) / TM);
    dim3 block(16, 16);
    sgemm_kernel<<<grid, block>>>(A, B, C, M, N, K, bias, epi, g, be, mn, vr);
}

extern "C" void kernel_launch(void* const* d_in, const int* in_sizes, int n_in,
                              void* d_out, int out_size) {
    // inputs in metadata order
    const float* x        = (const float*)d_in[0];
    const int*   ei       = (const int*)  d_in[1];
    const int*   batch    = (const int*)  d_in[2];
    const float* x_gen    = (const float*)d_in[3];
    const float* W1       = (const float*)d_in[4];
    const float* att_src1 = (const float*)d_in[5];
    const float* att_dst1 = (const float*)d_in[6];
    const float* bias1    = (const float*)d_in[7];
    const float* W2       = (const float*)d_in[8];
    const float* att_src2 = (const float*)d_in[9];
    const float* att_dst2 = (const float*)d_in[10];
    const float* bias2    = (const float*)d_in[11];
    const float* gW1      = (const float*)d_in[12];
    const float* gb1      = (const float*)d_in[13];
    const float* bn_gamma = (const float*)d_in[14];
    const float* bn_beta  = (const float*)d_in[15];
    const float* bn_mean  = (const float*)d_in[16];
    const float* bn_var   = (const float*)d_in[17];
    const float* gW2      = (const float*)d_in[18];
    const float* gb2      = (const float*)d_in[19];
    const float* fW1      = (const float*)d_in[20];
    const float* fb1      = (const float*)d_in[21];
    const float* fW2      = (const float*)d_in[22];
    const float* fb2      = (const float*)d_in[23];
    const float* fW3      = (const float*)d_in[24];
    const float* fb3      = (const float*)d_in[25];
    float* out = (float*)d_out;

    float *h1, *h2, *asrc, *adst, *emax, *denom, *psum, *cnt, *z1, *z2, *cbuf, *f1, *f2;
    cudaGetSymbolAddress((void**)&h1, g_h1);
    cudaGetSymbolAddress((void**)&h2, g_h2);
    cudaGetSymbolAddress((void**)&asrc, g_asrc);
    cudaGetSymbolAddress((void**)&adst, g_adst);
    cudaGetSymbolAddress((void**)&emax, g_emax);
    cudaGetSymbolAddress((void**)&denom, g_denom);
    cudaGetSymbolAddress((void**)&psum, g_psum);
    cudaGetSymbolAddress((void**)&cnt, g_cnt);
    cudaGetSymbolAddress((void**)&z1, g_z1);
    cudaGetSymbolAddress((void**)&z2, g_z2);
    cudaGetSymbolAddress((void**)&cbuf, g_cbuf);
    cudaGetSymbolAddress((void**)&f1, g_f1);
    cudaGetSymbolAddress((void**)&f2, g_f2);

    const int NH = NNODES * NHEADS;
    const int EH = NSELF * NHEADS;

    // ===== GAT layer 1 =====
    launch_sgemm(x, W1, h1, NNODES, GOUTD, FIN, nullptr, 0);
    attn_coef_kernel<<<(NH + 255) / 256, 256>>>(h1, att_src1, att_dst1, asrc, adst);
    launch_fill(emax, NH, -INFINITY);
    launch_fill(denom, NH, 0.f);
    launch_fill(h2, NNODES * GOUTD, 0.f);
    edge_max_kernel<<<(EH + 255) / 256, 256>>>(ei, asrc, adst, emax);
    edge_denom_kernel<<<(EH + 255) / 256, 256>>>(ei, asrc, adst, emax, denom);
    edge_agg_kernel<<<NSELF, 512>>>(ei, asrc, adst, emax, denom, h1, h2);
    bias_elu_kernel<<<(NNODES * GOUTD + 255) / 256, 256>>>(h2, bias1);

    // ===== GAT layer 2 =====
    launch_sgemm(h2, W2, h1, NNODES, GOUTD, GOUTD, nullptr, 0);
    attn_coef_kernel<<<(NH + 255) / 256, 256>>>(h1, att_src2, att_dst2, asrc, adst);
    launch_fill(emax, NH, -INFINITY);
    launch_fill(denom, NH, 0.f);
    launch_fill(h2, NNODES * GOUTD, 0.f);
    edge_max_kernel<<<(EH + 255) / 256, 256>>>(ei, asrc, adst, emax);
    edge_denom_kernel<<<(EH + 255) / 256, 256>>>(ei, asrc, adst, emax, denom);
    edge_agg_kernel<<<NSELF, 512>>>(ei, asrc, adst, emax, denom, h1, h2);
    bias_elu_kernel<<<(NNODES * GOUTD + 255) / 256, 256>>>(h2, bias2);

    // ===== global mean pool =====
    launch_fill(psum, NBATCH * GOUTD, 0.f);
    launch_fill(cnt, NBATCH, 0.f);
    pool_kernel<<<(NNODES * GOUTD + 255) / 256, 256>>>(h2, batch, psum, cnt);

    // ===== genomic encoder =====
    launch_sgemm(x_gen, gW1, z1, NBATCH, 128, 735, gb1, 3, bn_gamma, bn_beta, bn_mean, bn_var);
    launch_sgemm(z1, gW2, z2, NBATCH, GOUTD, 128, gb2, 2);

    // ===== concat + fusion MLP =====
    concat_kernel<<<(NBATCH * GOUTD + 255) / 256, 256>>>(psum, cnt, z2, cbuf);
    launch_sgemm(cbuf, fW1, f1, NBATCH, 256, 1024, fb1, 2);
    launch_sgemm(f1, fW2, f2, NBATCH, 128, 256, fb2, 2);
    final_dot_kernel<<<NBATCH, 32>>>(f2, fW3, fb3, out);
}

// round 2
// speedup vs baseline: 2.2739x; 2.2739x over previous
#include <cuda_runtime.h>
#include <math.h>
#include <stdint.h>

#define NNODES 65536
#define NEDGES 262144
#define NBATCH 2048
#define FIN    78
#define GOUTD  512
#define NHEADS 8
#define HIDD   64
#define NSELF  (NEDGES + NNODES)

// ---------------- scratch (device globals; no allocation allowed) ----------
__device__ float g_h1[(size_t)NNODES * GOUTD];
__device__ float g_h2[(size_t)NNODES * GOUTD];
__device__ float g_asrc[NNODES * NHEADS];
__device__ float g_adst[NNODES * NHEADS];
__device__ float g_cbuf[NBATCH * 1024];
__device__ float g_z1[NBATCH * 128];
__device__ float g_f1[NBATCH * 256];
__device__ float g_f2[NBATCH * 128];
// CSR scratch
__device__ int g_deg[NNODES];
__device__ int g_rowptr[NNODES + 1];
__device__ int g_cursor[NNODES];
__device__ int g_eidx[NSELF];
__device__ int g_blocksum[256];
__device__ int g_blockoff[256];

// ---------------- small utility kernels ----------------
__global__ void fill_int_kernel(int* p, int n, int v) {
    int i = blockIdx.x * blockDim.x + threadIdx.x;
    if (i < n) p[i] = v;
}

__device__ __forceinline__ void edge_nodes(const int* ei, int e, int& s, int& d) {
    if (e < NEDGES) { s = ei[e]; d = ei[NEDGES + e]; }
    else            { s = e - NEDGES; d = s; }
}

// ---------------- CSR construction ----------------
__global__ void count_kernel(const int* __restrict__ ei, int* __restrict__ deg) {
    int e = blockIdx.x * blockDim.x + threadIdx.x;
    if (e >= NSELF) return;
    int s, d; edge_nodes(ei, e, s, d);
    atomicAdd(&deg[d], 1);
}

// block-level inclusive scan: 256 blocks x 256 threads; writes rowptr[i+1]=local inclusive,
// blocksum[b] = block total
__global__ void scan1_kernel(const int* __restrict__ deg, int* __restrict__ rowptr,
                             int* __restrict__ blocksum) {
    __shared__ int sm[256];
    int b = blockIdx.x, t = threadIdx.x;
    int i = b * 256 + t;
    int v = deg[i];
    sm[t] = v;
    __syncthreads();
#pragma unroll
    for (int off = 1; off < 256; off <<= 1) {
        int add = (t >= off) ? sm[t - off] : 0;
        __syncthreads();
        sm[t] += add;
        __syncthreads();
    }
    rowptr[i + 1] = sm[t];
    if (t == 255) blocksum[b] = sm[t];
}

// single block exclusive scan over 256 block sums
__global__ void scan2_kernel(const int* __restrict__ blocksum, int* __restrict__ blockoff) {
    __shared__ int sm[256];
    int t = threadIdx.x;
    sm[t] = blocksum[t];
    __syncthreads();
#pragma unroll
    for (int off = 1; off < 256; off <<= 1) {
        int add = (t >= off) ? sm[t - off] : 0;
        __syncthreads();
        sm[t] += add;
        __syncthreads();
    }
    blockoff[t] = sm[t] - blocksum[t];   // exclusive
}

__global__ void scan3_kernel(int* __restrict__ rowptr, const int* __restrict__ blockoff,
                             int* __restrict__ cursor) {
    int i = blockIdx.x * blockDim.x + threadIdx.x;
    if (i == 0) rowptr[0] = 0;
    if (i < NNODES) {
        int b = i >> 8;
        rowptr[i + 1] += blockoff[b];
    }
    __syncthreads();
    if (i < NNODES) {
        // cursor[i] = rowptr[i] (start offset); rowptr[i] already final
        // note: rowptr[i] for i in this block's range is final because blockoff applied
        // rowptr[0] set above; for i>0 rowptr[i] computed by (possibly another) thread —
        // avoid race: recompute from rowptr[i+1]-deg is not available; instead compute directly:
    }
}

// safe cursor init (separate kernel so all rowptr updates are complete)
__global__ void cursor_kernel(const int* __restrict__ rowptr, int* __restrict__ cursor) {
    int i = blockIdx.x * blockDim.x + threadIdx.x;
    if (i < NNODES) cursor[i] = rowptr[i];
}

__global__ void scatter_kernel(const int* __restrict__ ei, int* __restrict__ cursor,
                               int* __restrict__ eidx) {
    int e = blockIdx.x * blockDim.x + threadIdx.x;
    if (e >= NSELF) return;
    int s, d; edge_nodes(ei, e, s, d);
    int pos = atomicAdd(&cursor[d], 1);
    eidx[pos] = e;
}

// per-node insertion sort of edge ids (determinism: fixed summation order)
__global__ void sortseg_kernel(const int* __restrict__ rowptr, int* __restrict__ eidx) {
    int n = blockIdx.x * blockDim.x + threadIdx.x;
    if (n >= NNODES) return;
    int s = rowptr[n], e = rowptr[n + 1];
    for (int i = s + 1; i < e; i++) {
        int key = eidx[i];
        int j = i - 1;
        while (j >= s && eidx[j] > key) { eidx[j + 1] = eidx[j]; j--; }
        eidx[j + 1] = key;
    }
}

// ---------------- SGEMM 128x128x8, 256 threads, 8x8 microtile ----------------
// C[M,N](ldc) = A[M,K] @ B[K,N]; M,N multiples of 128. epi: 0 none, 1 +bias,
// 2 +bias,relu, 3 +bias,BN,relu
#define BM 128
#define BN 128
#define BK 8
__global__ __launch_bounds__(256, 2)
void sgemm_kernel(const float* __restrict__ A, const float* __restrict__ B,
                  float* __restrict__ C, int M, int N, int K, int ldc,
                  const float* __restrict__ bias, int epi,
                  const float* __restrict__ bn_gamma, const float* __restrict__ bn_beta,
                  const float* __restrict__ bn_mean, const float* __restrict__ bn_var) {
    __shared__ float As[BK][BM];
    __shared__ float Bs[BK][BN];

    const int tid = threadIdx.x;
    const int row0 = blockIdx.y * BM;
    const int col0 = blockIdx.x * BN;

    // A load mapping: thread -> (am, ak..ak+3) scalars
    const int am = tid >> 1;
    const int ak = (tid & 1) * 4;
    // B load mapping: thread -> (bk, bn..bn+3) float4
    const int bk = tid >> 5;
    const int bn = (tid & 31) * 4;

    const int tm = (tid >> 4) << 3;
    const int tn = (tid & 15) << 3;

    float acc[8][8];
#pragma unroll
    for (int i = 0; i < 8; i++)
#pragma unroll
        for (int j = 0; j < 8; j++) acc[i][j] = 0.f;

    const int ntiles = (K + BK - 1) / BK;

    // prologue: load tile 0
    float ra[4];
    float4 rb;
    {
        const float* Arow = A + (size_t)(row0 + am) * K;
#pragma unroll
        for (int u = 0; u < 4; u++) {
            int gk = ak + u;
            ra[u] = (gk < K) ? Arow[gk] : 0.f;
        }
        if (bk < K) rb = *reinterpret_cast<const float4*>(B + (size_t)bk * N + col0 + bn);
        else        rb = make_float4(0.f, 0.f, 0.f, 0.f);
#pragma unroll
        for (int u = 0; u < 4; u++) As[ak + u][am] = ra[u];
        *reinterpret_cast<float4*>(&Bs[bk][bn]) = rb;
    }
    __syncthreads();

    for (int t = 0; t < ntiles; t++) {
        int k0n = (t + 1) * BK;
        if (t + 1 < ntiles) {
            const float* Arow = A + (size_t)(row0 + am) * K;
#pragma unroll
            for (int u = 0; u < 4; u++) {
                int gk = k0n + ak + u;
                ra[u] = (gk < K) ? Arow[gk] : 0.f;
            }
            int gbk = k0n + bk;
            if (gbk < K) rb = *reinterpret_cast<const float4*>(B + (size_t)gbk * N + col0 + bn);
            else         rb = make_float4(0.f, 0.f, 0.f, 0.f);
        }

#pragma unroll
        for (int kk = 0; kk < BK; kk++) {
            float4 a0 = *reinterpret_cast<const float4*>(&As[kk][tm]);
            float4 a1 = *reinterpret_cast<const float4*>(&As[kk][tm + 4]);
            float4 b0 = *reinterpret_cast<const float4*>(&Bs[kk][tn]);
            float4 b1 = *reinterpret_cast<const float4*>(&Bs[kk][tn + 4]);
            float a[8] = {a0.x, a0.y, a0.z, a0.w, a1.x, a1.y, a1.z, a1.w};
            float b[8] = {b0.x, b0.y, b0.z, b0.w, b1.x, b1.y, b1.z, b1.w};
#pragma unroll
            for (int i = 0; i < 8; i++)
#pragma unroll
                for (int j = 0; j < 8; j++) acc[i][j] = fmaf(a[i], b[j], acc[i][j]);
        }
        __syncthreads();
        if (t + 1 < ntiles) {
#pragma unroll
            for (int u = 0; u < 4; u++) As[ak + u][am] = ra[u];
            *reinterpret_cast<float4*>(&Bs[bk][bn]) = rb;
            __syncthreads();
        }
    }

    // epilogue
    float bb[8], g[8], be[8], mn[8], vr[8];
    if (epi >= 1) {
#pragma unroll
        for (int j = 0; j < 8; j++) bb[j] = bias[col0 + tn + j];
    }
    if (epi == 3) {
#pragma unroll
        for (int j = 0; j < 8; j++) {
            int c = col0 + tn + j;
            g[j] = bn_gamma[c]; be[j] = bn_beta[c]; mn[j] = bn_mean[c]; vr[j] = bn_var[c];
        }
    }
#pragma unroll
    for (int i = 0; i < 8; i++) {
        int gm = row0 + tm + i;
        float v[8];
#pragma unroll
        for (int j = 0; j < 8; j++) {
            float x = acc[i][j];
            if (epi >= 1) x += bb[j];
            if (epi == 3) x = (x - mn[j]) * (g[j] * rsqrtf(vr[j] + 1e-5f)) + be[j];
            if (epi >= 2) x = fmaxf(x, 0.f);
            v[j] = x;
        }
        float* Cp = C + (size_t)gm * ldc + col0 + tn;
        *reinterpret_cast<float4*>(Cp)     = make_float4(v[0], v[1], v[2], v[3]);
        *reinterpret_cast<float4*>(Cp + 4) = make_float4(v[4], v[5], v[6], v[7]);
    }
}

// ---------------- attention coefficients ----------------
__global__ void attn_coef_kernel(const float* __restrict__ h,
                                 const float* __restrict__ att_src,
                                 const float* __restrict__ att_dst,
                                 float* __restrict__ a_src, float* __restrict__ a_dst) {
    int idx = blockIdx.x * blockDim.x + threadIdx.x;
    if (idx >= NNODES * NHEADS) return;
    int n = idx >> 3, hd = idx & 7;
    const float* hp = h + (size_t)n * GOUTD + hd * HIDD;
    const float* as = att_src + hd * HIDD;
    const float* ad = att_dst + hd * HIDD;
    float s = 0.f, d = 0.f;
#pragma unroll 8
    for (int c = 0; c < HIDD; c++) {
        float v = hp[c];
        s = fmaf(v, as[c], s);
        d = fmaf(v, ad[c], d);
    }
    a_src[idx] = s;
    a_dst[idx] = d;
}

// ---------------- CSR aggregation: block per dst node, 256 threads ----------
// out[n] = ELU( sum_{e in in(n)} alpha_e * h[src(e)] + bias )
#define CH 32
__global__ __launch_bounds__(256)
void agg_kernel(const int* __restrict__ rowptr, const int* __restrict__ eidx,
                const int* __restrict__ ei,
                const float* __restrict__ asrc, const float* __restrict__ adst,
                const float* __restrict__ h, const float* __restrict__ bias,
                float* __restrict__ out) {
    const int n = blockIdx.x;
    const int t = threadIdx.x;
    const int start = rowptr[n];
    const int deg = rowptr[n + 1] - start;

    __shared__ int   sidx[CH];
    __shared__ float vbuf[CH][NHEADS];
    __shared__ float alpha[CH][NHEADS];
    __shared__ float adn[NHEADS];
    __shared__ float m8[NHEADS], dn8[NHEADS];

    if (t < NHEADS) adn[t] = adst[n * NHEADS + t];
    __syncthreads();

    // pass 1: online softmax stats (max + denom) per head
    float m = -INFINITY, dsum = 0.f;   // only meaningful for t < 8
    for (int c0 = 0; c0 < deg; c0 += CH) {
        int cnt = min(CH, deg - c0);
        if (t < cnt) {
            int e = eidx[start + c0 + t];
            sidx[t] = (e < NEDGES) ? ei[e] : (e - NEDGES);
        }
        __syncthreads();
        if (t < cnt * NHEADS) {
            int j = t >> 3, hd = t & 7;
            float v = asrc[sidx[j] * NHEADS + hd] + adn[hd];
            vbuf[j][hd] = (v > 0.f) ? v : 0.2f * v;
        }
        __syncthreads();
        if (t < NHEADS) {
            float cm = m;
            for (int j = 0; j < cnt; j++) cm = fmaxf(cm, vbuf[j][t]);
            dsum *= __expf(m - cm);
            for (int j = 0; j < cnt; j++) dsum += __expf(vbuf[j][t] - cm);
            m = cm;
        }
        __syncthreads();
    }
    if (t < NHEADS) { m8[t] = m; dn8[t] = dsum + 1e-16f; }
    __syncthreads();

    // pass 2: alpha + accumulate (each thread handles 2 channels)
    const int c0ch = t * 2;
    const int head = t >> 5;          // c0ch/64
    float2 acc = make_float2(0.f, 0.f);
    for (int c0 = 0; c0 < deg; c0 += CH) {
        int cnt = min(CH, deg - c0);
        if (t < cnt) {
            int e = eidx[start + c0 + t];
            sidx[t] = (e < NEDGES) ? ei[e] : (e - NEDGES);
        }
        __syncthreads();
        if (t < cnt * NHEADS) {
            int j = t >> 3, hd = t & 7;
            float v = asrc[sidx[j] * NHEADS + hd] + adn[hd];
            v = (v > 0.f) ? v : 0.2f * v;
            alpha[j][hd] = __expf(v - m8[hd]) / dn8[hd];
        }
        __syncthreads();
        for (int j = 0; j < cnt; j++) {
            float a = alpha[j][head];
            float2 hv = *reinterpret_cast<const float2*>(h + (size_t)sidx[j] * GOUTD + c0ch);
            acc.x = fmaf(hv.x, a, acc.x);
            acc.y = fmaf(hv.y, a, acc.y);
        }
        __syncthreads();
    }

    // epilogue: bias + ELU
    float vx = acc.x + bias[c0ch];
    float vy = acc.y + bias[c0ch + 1];
    vx = (vx > 0.f) ? vx : (__expf(vx) - 1.f);
    vy = (vy > 0.f) ? vy : (__expf(vy) - 1.f);
    *reinterpret_cast<float2*>(out + (size_t)n * GOUTD + c0ch) = make_float2(vx, vy);
}

// ---------------- pooling (block per graph, binary search on sorted batch) ---
__device__ __forceinline__ int lower_bound_dev(const int* a, int n, int key) {
    int lo = 0, hi = n;
    while (lo < hi) {
        int mid = (lo + hi) >> 1;
        if (a[mid] < key) lo = mid + 1; else hi = mid;
    }
    return lo;
}

__global__ void pool_kernel(const float* __restrict__ h, const int* __restrict__ batch,
                            float* __restrict__ cbuf) {
    int b = blockIdx.x;
    int t = threadIdx.x;                       // 256 threads, 2 channels each
    int lo = lower_bound_dev(batch, NNODES, b);
    int hi = lower_bound_dev(batch, NNODES, b + 1);
    float2 acc = make_float2(0.f, 0.f);
    for (int r = lo; r < hi; r++) {
        float2 hv = *reinterpret_cast<const float2*>(h + (size_t)r * GOUTD + t * 2);
        acc.x += hv.x; acc.y += hv.y;
    }
    float inv = 1.f / fmaxf((float)(hi - lo), 1.f);
    *reinterpret_cast<float2*>(cbuf + (size_t)b * 1024 + t * 2) =
        make_float2(acc.x * inv, acc.y * inv);
}

// ---------------- final dot ----------------
__global__ void final_dot_kernel(const float* __restrict__ f2, const float* __restrict__ w,
                                 const float* __restrict__ b, float* __restrict__ out) {
    int row = blockIdx.x;
    int lane = threadIdx.x;
    float s = 0.f;
    for (int c = lane; c < 128; c += 32) s = fmaf(f2[row * 128 + c], w[c], s);
#pragma unroll
    for (int off = 16; off > 0; off >>= 1) s += __shfl_xor_sync(0xFFFFFFFFu, s, off);
    if (lane == 0) out[row] = s + b[0];
}

// ---------------- host orchestration ----------------
static inline void launch_sgemm(const float* A, const float* B, float* C, int M, int N, int K,
                                int ldc, const float* bias, int epi,
                                const float* g = nullptr, const float* be = nullptr,
                                const float* mn = nullptr, const float* vr = nullptr) {
    dim3 grid(N / BN, M / BM);
    sgemm_kernel<<<grid, 256>>>(A, B, C, M, N, K, ldc, bias, epi, g, be, mn, vr);
}

extern "C" void kernel_launch(void* const* d_in, const int* in_sizes, int n_in,
                              void* d_out, int out_size) {
    const float* x        = (const float*)d_in[0];
    const int*   ei       = (const int*)  d_in[1];
    const int*   batch    = (const int*)  d_in[2];
    const float* x_gen    = (const float*)d_in[3];
    const float* W1       = (const float*)d_in[4];
    const float* att_src1 = (const float*)d_in[5];
    const float* att_dst1 = (const float*)d_in[6];
    const float* bias1    = (const float*)d_in[7];
    const float* W2       = (const float*)d_in[8];
    const float* att_src2 = (const float*)d_in[9];
    const float* att_dst2 = (const float*)d_in[10];
    const float* bias2    = (const float*)d_in[11];
    const float* gW1      = (const float*)d_in[12];
    const float* gb1      = (const float*)d_in[13];
    const float* bn_gamma = (const float*)d_in[14];
    const float* bn_beta  = (const float*)d_in[15];
    const float* bn_mean  = (const float*)d_in[16];
    const float* bn_var   = (const float*)d_in[17];
    const float* gW2      = (const float*)d_in[18];
    const float* gb2      = (const float*)d_in[19];
    const float* fW1      = (const float*)d_in[20];
    const float* fb1      = (const float*)d_in[21];
    const float* fW2      = (const float*)d_in[22];
    const float* fb2      = (const float*)d_in[23];
    const float* fW3      = (const float*)d_in[24];
    const float* fb3      = (const float*)d_in[25];
    float* out = (float*)d_out;

    float *h1, *h2, *asrc, *adst, *cbuf, *z1, *f1, *f2;
    int *deg, *rowptr, *cursor, *eidx, *blocksum, *blockoff;
    cudaGetSymbolAddress((void**)&h1, g_h1);
    cudaGetSymbolAddress((void**)&h2, g_h2);
    cudaGetSymbolAddress((void**)&asrc, g_asrc);
    cudaGetSymbolAddress((void**)&adst, g_adst);
    cudaGetSymbolAddress((void**)&cbuf, g_cbuf);
    cudaGetSymbolAddress((void**)&z1, g_z1);
    cudaGetSymbolAddress((void**)&f1, g_f1);
    cudaGetSymbolAddress((void**)&f2, g_f2);
    cudaGetSymbolAddress((void**)&deg, g_deg);
    cudaGetSymbolAddress((void**)&rowptr, g_rowptr);
    cudaGetSymbolAddress((void**)&cursor, g_cursor);
    cudaGetSymbolAddress((void**)&eidx, g_eidx);
    cudaGetSymbolAddress((void**)&blocksum, g_blocksum);
    cudaGetSymbolAddress((void**)&blockoff, g_blockoff);

    const int NH = NNODES * NHEADS;

    // ===== CSR build (once; same graph for both layers) =====
    fill_int_kernel<<<NNODES / 256, 256>>>(deg, NNODES, 0);
    count_kernel<<<(NSELF + 255) / 256, 256>>>(ei, deg);
    scan1_kernel<<<256, 256>>>(deg, rowptr, blocksum);
    scan2_kernel<<<1, 256>>>(blocksum, blockoff);
    scan3_kernel<<<NNODES / 256, 256>>>(rowptr, blockoff, cursor);
    cursor_kernel<<<NNODES / 256, 256>>>(rowptr, cursor);
    scatter_kernel<<<(NSELF + 255) / 256, 256>>>(ei, cursor, eidx);
    sortseg_kernel<<<NNODES / 256, 256>>>(rowptr, eidx);

    // ===== GAT layer 1 =====
    launch_sgemm(x, W1, h1, NNODES, GOUTD, FIN, GOUTD, nullptr, 0);
    attn_coef_kernel<<<(NH + 255) / 256, 256>>>(h1, att_src1, att_dst1, asrc, adst);
    agg_kernel<<<NNODES, 256>>>(rowptr, eidx, ei, asrc, adst, h1, bias1, h2);

    // ===== GAT layer 2 =====
    launch_sgemm(h2, W2, h1, NNODES, GOUTD, GOUTD, GOUTD, nullptr, 0);
    attn_coef_kernel<<<(NH + 255) / 256, 256>>>(h1, att_src2, att_dst2, asrc, adst);
    agg_kernel<<<NNODES, 256>>>(rowptr, eidx, ei, asrc, adst, h1, bias2, h2);

    // ===== global mean pool -> first half of concat buffer =====
    pool_kernel<<<NBATCH, 256>>>(h2, batch, cbuf);

    // ===== genomic encoder; second GEMM writes second half of concat =====
    launch_sgemm(x_gen, gW1, z1, NBATCH, 128, 735, 128, gb1, 3, bn_gamma, bn_beta, bn_mean, bn_var);
    launch_sgemm(z1, gW2, cbuf + 512, NBATCH, GOUTD, 128, 1024, gb2, 2);

    // ===== fusion MLP =====
    launch_sgemm(cbuf, fW1, f1, NBATCH, 256, 1024, 256, fb1, 2);
    launch_sgemm(f1, fW2, f2, NBATCH, 128, 256, 128, fb2, 2);
    final_dot_kernel<<<NBATCH, 32>>>(f2, fW3, fb3, out);
}

// round 3
// speedup vs baseline: 4.6869x; 2.0611x over previous
#include <cuda_runtime.h>
#include <math.h>
#include <stdint.h>

#define NNODES 65536
#define NEDGES 262144
#define NBATCH 2048
#define FIN    78
#define GOUTD  512
#define NHEADS 8
#define HIDD   64
#define NSELF  (NEDGES + NNODES)

// ---------------- scratch (device globals; no allocation allowed) ----------
__device__ float g_h1[(size_t)NNODES * GOUTD];
__device__ float g_h2[(size_t)NNODES * GOUTD];
__device__ float g_asrc[NNODES * NHEADS];
__device__ float g_adst[NNODES * NHEADS];
__device__ float g_cbuf[NBATCH * 1024];
__device__ float g_z1[NBATCH * 128];
__device__ float g_f1[NBATCH * 256];
__device__ float g_f2[NBATCH * 128];
// CSR scratch
__device__ int g_deg[NNODES];
__device__ int g_rowptr[NNODES + 1];
__device__ int g_cursor[NNODES];
__device__ int g_eidx[NSELF];
__device__ int g_srcarr[NSELF];
__device__ int g_blocksum[256];
__device__ int g_blockoff[256];

// ---------------- small utility kernels ----------------
__global__ void fill_int_kernel(int* p, int n, int v) {
    int i = blockIdx.x * blockDim.x + threadIdx.x;
    if (i < n) p[i] = v;
}

__device__ __forceinline__ void edge_nodes(const int* ei, int e, int& s, int& d) {
    if (e < NEDGES) { s = ei[e]; d = ei[NEDGES + e]; }
    else            { s = e - NEDGES; d = s; }
}

// ---------------- CSR construction ----------------
__global__ void count_kernel(const int* __restrict__ ei, int* __restrict__ deg) {
    int e = blockIdx.x * blockDim.x + threadIdx.x;
    if (e >= NSELF) return;
    int s, d; edge_nodes(ei, e, s, d);
    atomicAdd(&deg[d], 1);
}

__global__ void scan1_kernel(const int* __restrict__ deg, int* __restrict__ rowptr,
                             int* __restrict__ blocksum) {
    __shared__ int sm[256];
    int b = blockIdx.x, t = threadIdx.x;
    int i = b * 256 + t;
    sm[t] = deg[i];
    __syncthreads();
#pragma unroll
    for (int off = 1; off < 256; off <<= 1) {
        int add = (t >= off) ? sm[t - off] : 0;
        __syncthreads();
        sm[t] += add;
        __syncthreads();
    }
    rowptr[i + 1] = sm[t];
    if (t == 255) blocksum[b] = sm[t];
}

__global__ void scan2_kernel(const int* __restrict__ blocksum, int* __restrict__ blockoff) {
    __shared__ int sm[256];
    int t = threadIdx.x;
    sm[t] = blocksum[t];
    __syncthreads();
#pragma unroll
    for (int off = 1; off < 256; off <<= 1) {
        int add = (t >= off) ? sm[t - off] : 0;
        __syncthreads();
        sm[t] += add;
        __syncthreads();
    }
    blockoff[t] = sm[t] - blocksum[t];
}

__global__ void scan3_kernel(int* __restrict__ rowptr, const int* __restrict__ blockoff) {
    int i = blockIdx.x * blockDim.x + threadIdx.x;
    if (i == 0) rowptr[0] = 0;
    if (i < NNODES) rowptr[i + 1] += blockoff[i >> 8];
}

__global__ void cursor_kernel(const int* __restrict__ rowptr, int* __restrict__ cursor) {
    int i = blockIdx.x * blockDim.x + threadIdx.x;
    if (i < NNODES) cursor[i] = rowptr[i];
}

__global__ void scatter_kernel(const int* __restrict__ ei, int* __restrict__ cursor,
                               int* __restrict__ eidx) {
    int e = blockIdx.x * blockDim.x + threadIdx.x;
    if (e >= NSELF) return;
    int s, d; edge_nodes(ei, e, s, d);
    int pos = atomicAdd(&cursor[d], 1);
    eidx[pos] = e;
}

__global__ void sortseg_kernel(const int* __restrict__ rowptr, int* __restrict__ eidx) {
    int n = blockIdx.x * blockDim.x + threadIdx.x;
    if (n >= NNODES) return;
    int s = rowptr[n], e = rowptr[n + 1];
    for (int i = s + 1; i < e; i++) {
        int key = eidx[i];
        int j = i - 1;
        while (j >= s && eidx[j] > key) { eidx[j + 1] = eidx[j]; j--; }
        eidx[j + 1] = key;
    }
}

__global__ void srcmap_kernel(const int* __restrict__ eidx, const int* __restrict__ ei,
                              int* __restrict__ srcarr) {
    int p = blockIdx.x * blockDim.x + threadIdx.x;
    if (p >= NSELF) return;
    int e = eidx[p];
    srcarr[p] = (e < NEDGES) ? ei[e] : (e - NEDGES);
}

// ---------------- tf32 tensor-core GEMM ----------------
// C[M,N](ldc) = A[M,K]@B[K,N]. Requires M%128==0, N%128==0, K arbitrary.
// epi: 0 none, 1 +bias, 2 +bias,relu, 3 +bias,BN,relu
#define TBM 128
#define TBN 128
#define TBK 16
#define APAD 20
#define BPAD 136

__device__ __forceinline__ uint32_t f2tf32(float f) {
    uint32_t r;
    asm("cvt.rna.tf32.f32 %0, %1;" : "=r"(r) : "f"(f));
    return r;
}

__device__ __forceinline__ void mma_tf32(float c[4], const uint32_t a[4], const uint32_t b[2]) {
    asm volatile(
        "mma.sync.aligned.m16n8k8.row.col.f32.tf32.tf32.f32 "
        "{%0,%1,%2,%3}, {%4,%5,%6,%7}, {%8,%9}, {%0,%1,%2,%3};"
        : "+f"(c[0]), "+f"(c[1]), "+f"(c[2]), "+f"(c[3])
        : "r"(a[0]), "r"(a[1]), "r"(a[2]), "r"(a[3]), "r"(b[0]), "r"(b[1]));
}

__global__ __launch_bounds__(256)
void tgemm_kernel(const float* __restrict__ A, const float* __restrict__ B,
                  float* __restrict__ C, int M, int N, int K, int ldc,
                  const float* __restrict__ bias, int epi,
                  const float* __restrict__ bn_gamma, const float* __restrict__ bn_beta,
                  const float* __restrict__ bn_mean, const float* __restrict__ bn_var) {
    __shared__ uint32_t As[TBM][APAD];   // [m][k], pad 20 -> conflict-free frag loads
    __shared__ uint32_t Bs[TBK][BPAD];   // [k][n], pad 136 -> conflict-free frag loads

    const int tid = threadIdx.x;
    const int row0 = blockIdx.y * TBM;
    const int col0 = blockIdx.x * TBN;
    const int warp = tid >> 5, lane = tid & 31;
    const int g = lane >> 2, t4 = lane & 3;
    const int wm = warp & 1, wn = warp >> 1;    // 2 x 4 warp grid -> 64x32 per warp

    // global->smem mappings
    const int am = tid >> 1, ak = (tid & 1) * 8;      // A: 128 x 16
    const int kb = tid >> 4, nb = (tid & 15) * 8;     // B: 16 x 128

    float acc[4][4][4];
#pragma unroll
    for (int i = 0; i < 4; i++)
#pragma unroll
        for (int j = 0; j < 4; j++)
#pragma unroll
            for (int l = 0; l < 4; l++) acc[i][j][l] = 0.f;

    const int ntiles = (K + TBK - 1) / TBK;
    const bool vec4 = ((K & 3) == 0);
    const float* Arow = A + (size_t)(row0 + am) * K;

    float ra[8];
    float rb[8];

    // prologue: tile 0 -> regs
    {
        if (vec4 && ak + 7 < K) {
            float4 v0 = *reinterpret_cast<const float4*>(Arow + ak);
            float4 v1 = *reinterpret_cast<const float4*>(Arow + ak + 4);
            ra[0]=v0.x; ra[1]=v0.y; ra[2]=v0.z; ra[3]=v0.w;
            ra[4]=v1.x; ra[5]=v1.y; ra[6]=v1.z; ra[7]=v1.w;
        } else {
#pragma unroll
            for (int u = 0; u < 8; u++) { int gk = ak + u; ra[u] = (gk < K) ? Arow[gk] : 0.f; }
        }
        if (kb < K) {
            const float* Bp = B + (size_t)kb * N + col0 + nb;
            float4 v0 = *reinterpret_cast<const float4*>(Bp);
            float4 v1 = *reinterpret_cast<const float4*>(Bp + 4);
            rb[0]=v0.x; rb[1]=v0.y; rb[2]=v0.z; rb[3]=v0.w;
            rb[4]=v1.x; rb[5]=v1.y; rb[6]=v1.z; rb[7]=v1.w;
        } else {
#pragma unroll
            for (int u = 0; u < 8; u++) rb[u] = 0.f;
        }
#pragma unroll
        for (int u = 0; u < 8; u++) As[am][ak + u] = f2tf32(ra[u]);
#pragma unroll
        for (int u = 0; u < 8; u++) Bs[kb][nb + u] = f2tf32(rb[u]);
    }
    __syncthreads();

    for (int ti = 0; ti < ntiles; ti++) {
        if (ti + 1 < ntiles) {
            int k0 = (ti + 1) * TBK;
            if (vec4 && k0 + ak + 7 < K) {
                float4 v0 = *reinterpret_cast<const float4*>(Arow + k0 + ak);
                float4 v1 = *reinterpret_cast<const float4*>(Arow + k0 + ak + 4);
                ra[0]=v0.x; ra[1]=v0.y; ra[2]=v0.z; ra[3]=v0.w;
                ra[4]=v1.x; ra[5]=v1.y; ra[6]=v1.z; ra[7]=v1.w;
            } else {
#pragma unroll
                for (int u = 0; u < 8; u++) { int gk = k0 + ak + u; ra[u] = (gk < K) ? Arow[gk] : 0.f; }
            }
            int gkb = k0 + kb;
            if (gkb < K) {
                const float* Bp = B + (size_t)gkb * N + col0 + nb;
                float4 v0 = *reinterpret_cast<const float4*>(Bp);
                float4 v1 = *reinterpret_cast<const float4*>(Bp + 4);
                rb[0]=v0.x; rb[1]=v0.y; rb[2]=v0.z; rb[3]=v0.w;
                rb[4]=v1.x; rb[5]=v1.y; rb[6]=v1.z; rb[7]=v1.w;
            } else {
#pragma unroll
                for (int u = 0; u < 8; u++) rb[u] = 0.f;
            }
        }

#pragma unroll
        for (int k8 = 0; k8 < TBK; k8 += 8) {
            uint32_t af[4][4];
            uint32_t bf[4][2];
#pragma unroll
            for (int mt = 0; mt < 4; mt++) {
                int mbase = wm * 64 + mt * 16;
                af[mt][0] = As[mbase + g][k8 + t4];
                af[mt][1] = As[mbase + g + 8][k8 + t4];
                af[mt][2] = As[mbase + g][k8 + t4 + 4];
                af[mt][3] = As[mbase + g + 8][k8 + t4 + 4];
            }
#pragma unroll
            for (int nt = 0; nt < 4; nt++) {
                int nbase = wn * 32 + nt * 8;
                bf[nt][0] = Bs[k8 + t4][nbase + g];
                bf[nt][1] = Bs[k8 + t4 + 4][nbase + g];
            }
#pragma unroll
            for (int mt = 0; mt < 4; mt++)
#pragma unroll
                for (int nt = 0; nt < 4; nt++)
                    mma_tf32(acc[mt][nt], af[mt], bf[nt]);
        }
        __syncthreads();
        if (ti + 1 < ntiles) {
#pragma unroll
            for (int u = 0; u < 8; u++) As[am][ak + u] = f2tf32(ra[u]);
#pragma unroll
            for (int u = 0; u < 8; u++) Bs[kb][nb + u] = f2tf32(rb[u]);
            __syncthreads();
        }
    }

    // epilogue
#pragma unroll
    for (int mt = 0; mt < 4; mt++) {
        int r0 = row0 + wm * 64 + mt * 16 + g;
        int r1 = r0 + 8;
#pragma unroll
        for (int nt = 0; nt < 4; nt++) {
            int c = col0 + wn * 32 + nt * 8 + 2 * t4;
            float v[4] = {acc[mt][nt][0], acc[mt][nt][1], acc[mt][nt][2], acc[mt][nt][3]};
            if (epi >= 1) {
                float b0 = bias[c], b1 = bias[c + 1];
                v[0] += b0; v[1] += b1; v[2] += b0; v[3] += b1;
            }
            if (epi == 3) {
                float s0 = bn_gamma[c] * rsqrtf(bn_var[c] + 1e-5f);
                float s1 = bn_gamma[c + 1] * rsqrtf(bn_var[c + 1] + 1e-5f);
                float m0 = bn_mean[c], m1 = bn_mean[c + 1];
                float e0 = bn_beta[c], e1 = bn_beta[c + 1];
                v[0] = (v[0] - m0) * s0 + e0; v[1] = (v[1] - m1) * s1 + e1;
                v[2] = (v[2] - m0) * s0 + e0; v[3] = (v[3] - m1) * s1 + e1;
            }
            if (epi >= 2) {
#pragma unroll
                for (int l = 0; l < 4; l++) v[l] = fmaxf(v[l], 0.f);
            }
            *reinterpret_cast<float2*>(C + (size_t)r0 * ldc + c) = make_float2(v[0], v[1]);
            *reinterpret_cast<float2*>(C + (size_t)r1 * ldc + c) = make_float2(v[2], v[3]);
        }
    }
}

// ---------------- attention coefficients: warp per node, coalesced ----------
__global__ __launch_bounds__(256)
void attn_coef_kernel(const float* __restrict__ h,
                      const float* __restrict__ att_src,
                      const float* __restrict__ att_dst,
                      float* __restrict__ a_src, float* __restrict__ a_dst) {
    int n = blockIdx.x * 8 + (threadIdx.x >> 5);
    int lane = threadIdx.x & 31;
    int head = lane >> 2;
    const float* hp = h + (size_t)n * GOUTD + lane * 16;
    const float* as = att_src + head * HIDD + (lane & 3) * 16;
    const float* ad = att_dst + head * HIDD + (lane & 3) * 16;
    float s = 0.f, d = 0.f;
#pragma unroll
    for (int q = 0; q < 4; q++) {
        float4 hv = *reinterpret_cast<const float4*>(hp + q * 4);
        float4 av = *reinterpret_cast<const float4*>(as + q * 4);
        float4 dv = *reinterpret_cast<const float4*>(ad + q * 4);
        s = fmaf(hv.x, av.x, fmaf(hv.y, av.y, fmaf(hv.z, av.z, fmaf(hv.w, av.w, s))));
        d = fmaf(hv.x, dv.x, fmaf(hv.y, dv.y, fmaf(hv.z, dv.z, fmaf(hv.w, dv.w, d))));
    }
    s += __shfl_xor_sync(0xFFFFFFFFu, s, 1);
    s += __shfl_xor_sync(0xFFFFFFFFu, s, 2);
    d += __shfl_xor_sync(0xFFFFFFFFu, d, 1);
    d += __shfl_xor_sync(0xFFFFFFFFu, d, 2);
    if ((lane & 3) == 0) {
        a_src[n * NHEADS + head] = s;
        a_dst[n * NHEADS + head] = d;
    }
}

// ---------------- CSR aggregation: block per dst node ----------
#define CH 32
__global__ __launch_bounds__(256)
void agg_kernel(const int* __restrict__ rowptr, const int* __restrict__ srcarr,
                const float* __restrict__ asrc, const float* __restrict__ adst,
                const float* __restrict__ h, const float* __restrict__ bias,
                float* __restrict__ out) {
    const int n = blockIdx.x;
    const int t = threadIdx.x;
    const int start = rowptr[n];
    const int deg = rowptr[n + 1] - start;

    __shared__ int   sidx[CH];
    __shared__ float vbuf[CH][NHEADS];
    __shared__ float adn[NHEADS];
    __shared__ float m8[NHEADS], dn8[NHEADS];

    if (t < NHEADS) adn[t] = adst[n * NHEADS + t];

    const int c0ch = t * 2;
    const int head = t >> 5;
    float2 acc = make_float2(0.f, 0.f);

    if (deg <= CH) {
        // fast path: one chunk, reuse leaky-relu values
        if (t < deg) sidx[t] = srcarr[start + t];
        __syncthreads();
        if (t < deg * NHEADS) {
            int j = t >> 3, hd = t & 7;
            float v = asrc[sidx[j] * NHEADS + hd] + adn[hd];
            vbuf[j][hd] = (v > 0.f) ? v : 0.2f * v;
        }
        __syncthreads();
        if (t < NHEADS) {
            float m = -INFINITY;
            for (int j = 0; j < deg; j++) m = fmaxf(m, vbuf[j][t]);
            float dsum = 0.f;
            for (int j = 0; j < deg; j++) dsum += __expf(vbuf[j][t] - m);
            m8[t] = m; dn8[t] = dsum + 1e-16f;
        }
        __syncthreads();
        if (t < deg * NHEADS) {
            int j = t >> 3, hd = t & 7;
            vbuf[j][hd] = __expf(vbuf[j][hd] - m8[hd]) / dn8[hd];
        }
        __syncthreads();
        for (int j = 0; j < deg; j++) {
            float a = vbuf[j][head];
            float2 hv = *reinterpret_cast<const float2*>(h + (size_t)sidx[j] * GOUTD + c0ch);
            acc.x = fmaf(hv.x, a, acc.x);
            acc.y = fmaf(hv.y, a, acc.y);
        }
    } else {
        // general path: two passes in chunks
        __syncthreads();
        float m = -INFINITY, dsum = 0.f;
        for (int c0 = 0; c0 < deg; c0 += CH) {
            int cnt = min(CH, deg - c0);
            if (t < cnt) sidx[t] = srcarr[start + c0 + t];
            __syncthreads();
            if (t < cnt * NHEADS) {
                int j = t >> 3, hd = t & 7;
                float v = asrc[sidx[j] * NHEADS + hd] + adn[hd];
                vbuf[j][hd] = (v > 0.f) ? v : 0.2f * v;
            }
            __syncthreads();
            if (t < NHEADS) {
                float cm = m;
                for (int j = 0; j < cnt; j++) cm = fmaxf(cm, vbuf[j][t]);
                dsum *= __expf(m - cm);
                for (int j = 0; j < cnt; j++) dsum += __expf(vbuf[j][t] - cm);
                m = cm;
            }
            __syncthreads();
        }
        if (t < NHEADS) { m8[t] = m; dn8[t] = dsum + 1e-16f; }
        __syncthreads();
        for (int c0 = 0; c0 < deg; c0 += CH) {
            int cnt = min(CH, deg - c0);
            if (t < cnt) sidx[t] = srcarr[start + c0 + t];
            __syncthreads();
            if (t < cnt * NHEADS) {
                int j = t >> 3, hd = t & 7;
                float v = asrc[sidx[j] * NHEADS + hd] + adn[hd];
                v = (v > 0.f) ? v : 0.2f * v;
                vbuf[j][hd] = __expf(v - m8[hd]) / dn8[hd];
            }
            __syncthreads();
            for (int j = 0; j < cnt; j++) {
                float a = vbuf[j][head];
                float2 hv = *reinterpret_cast<const float2*>(h + (size_t)sidx[j] * GOUTD + c0ch);
                acc.x = fmaf(hv.x, a, acc.x);
                acc.y = fmaf(hv.y, a, acc.y);
            }
            __syncthreads();
        }
    }

    float vx = acc.x + bias[c0ch];
    float vy = acc.y + bias[c0ch + 1];
    vx = (vx > 0.f) ? vx : (__expf(vx) - 1.f);
    vy = (vy > 0.f) ? vy : (__expf(vy) - 1.f);
    *reinterpret_cast<float2*>(out + (size_t)n * GOUTD + c0ch) = make_float2(vx, vy);
}

// ---------------- pooling ----------------
__device__ __forceinline__ int lower_bound_dev(const int* a, int n, int key) {
    int lo = 0, hi = n;
    while (lo < hi) {
        int mid = (lo + hi) >> 1;
        if (a[mid] < key) lo = mid + 1; else hi = mid;
    }
    return lo;
}

__global__ void pool_kernel(const float* __restrict__ h, const int* __restrict__ batch,
                            float* __restrict__ cbuf) {
    int b = blockIdx.x;
    int t = threadIdx.x;
    int lo = lower_bound_dev(batch, NNODES, b);
    int hi = lower_bound_dev(batch, NNODES, b + 1);
    float2 acc = make_float2(0.f, 0.f);
    for (int r = lo; r < hi; r++) {
        float2 hv = *reinterpret_cast<const float2*>(h + (size_t)r * GOUTD + t * 2);
        acc.x += hv.x; acc.y += hv.y;
    }
    float inv = 1.f / fmaxf((float)(hi - lo), 1.f);
    *reinterpret_cast<float2*>(cbuf + (size_t)b * 1024 + t * 2) =
        make_float2(acc.x * inv, acc.y * inv);
}

// ---------------- final dot ----------------
__global__ void final_dot_kernel(const float* __restrict__ f2, const float* __restrict__ w,
                                 const float* __restrict__ b, float* __restrict__ out) {
    int row = blockIdx.x;
    int lane = threadIdx.x;
    float s = 0.f;
    for (int c = lane; c < 128; c += 32) s = fmaf(f2[row * 128 + c], w[c], s);
#pragma unroll
    for (int off = 16; off > 0; off >>= 1) s += __shfl_xor_sync(0xFFFFFFFFu, s, off);
    if (lane == 0) out[row] = s + b[0];
}

// ---------------- host orchestration ----------------
static inline void launch_tgemm(const float* A, const float* B, float* C, int M, int N, int K,
                                int ldc, const float* bias, int epi,
                                const float* g = nullptr, const float* be = nullptr,
                                const float* mn = nullptr, const float* vr = nullptr) {
    dim3 grid(N / TBN, M / TBM);
    tgemm_kernel<<<grid, 256>>>(A, B, C, M, N, K, ldc, bias, epi, g, be, mn, vr);
}

extern "C" void kernel_launch(void* const* d_in, const int* in_sizes, int n_in,
                              void* d_out, int out_size) {
    const float* x        = (const float*)d_in[0];
    const int*   ei       = (const int*)  d_in[1];
    const int*   batch    = (const int*)  d_in[2];
    const float* x_gen    = (const float*)d_in[3];
    const float* W1       = (const float*)d_in[4];
    const float* att_src1 = (const float*)d_in[5];
    const float* att_dst1 = (const float*)d_in[6];
    const float* bias1    = (const float*)d_in[7];
    const float* W2       = (const float*)d_in[8];
    const float* att_src2 = (const float*)d_in[9];
    const float* att_dst2 = (const float*)d_in[10];
    const float* bias2    = (const float*)d_in[11];
    const float* gW1      = (const float*)d_in[12];
    const float* gb1      = (const float*)d_in[13];
    const float* bn_gamma = (const float*)d_in[14];
    const float* bn_beta  = (const float*)d_in[15];
    const float* bn_mean  = (const float*)d_in[16];
    const float* bn_var   = (const float*)d_in[17];
    const float* gW2      = (const float*)d_in[18];
    const float* gb2      = (const float*)d_in[19];
    const float* fW1      = (const float*)d_in[20];
    const float* fb1      = (const float*)d_in[21];
    const float* fW2      = (const float*)d_in[22];
    const float* fb2      = (const float*)d_in[23];
    const float* fW3      = (const float*)d_in[24];
    const float* fb3      = (const float*)d_in[25];
    float* out = (float*)d_out;

    float *h1, *h2, *asrc, *adst, *cbuf, *z1, *f1, *f2;
    int *deg, *rowptr, *cursor, *eidx, *srcarr, *blocksum, *blockoff;
    cudaGetSymbolAddress((void**)&h1, g_h1);
    cudaGetSymbolAddress((void**)&h2, g_h2);
    cudaGetSymbolAddress((void**)&asrc, g_asrc);
    cudaGetSymbolAddress((void**)&adst, g_adst);
    cudaGetSymbolAddress((void**)&cbuf, g_cbuf);
    cudaGetSymbolAddress((void**)&z1, g_z1);
    cudaGetSymbolAddress((void**)&f1, g_f1);
    cudaGetSymbolAddress((void**)&f2, g_f2);
    cudaGetSymbolAddress((void**)&deg, g_deg);
    cudaGetSymbolAddress((void**)&rowptr, g_rowptr);
    cudaGetSymbolAddress((void**)&cursor, g_cursor);
    cudaGetSymbolAddress((void**)&eidx, g_eidx);
    cudaGetSymbolAddress((void**)&srcarr, g_srcarr);
    cudaGetSymbolAddress((void**)&blocksum, g_blocksum);
    cudaGetSymbolAddress((void**)&blockoff, g_blockoff);

    // ===== CSR build (same graph for both layers) =====
    fill_int_kernel<<<NNODES / 256, 256>>>(deg, NNODES, 0);
    count_kernel<<<(NSELF + 255) / 256, 256>>>(ei, deg);
    scan1_kernel<<<256, 256>>>(deg, rowptr, blocksum);
    scan2_kernel<<<1, 256>>>(blocksum, blockoff);
    scan3_kernel<<<NNODES / 256, 256>>>(rowptr, blockoff);
    cursor_kernel<<<NNODES / 256, 256>>>(rowptr, cursor);
    scatter_kernel<<<(NSELF + 255) / 256, 256>>>(ei, cursor, eidx);
    sortseg_kernel<<<NNODES / 256, 256>>>(rowptr, eidx);
    srcmap_kernel<<<(NSELF + 255) / 256, 256>>>(eidx, ei, srcarr);

    // ===== GAT layer 1 =====
    launch_tgemm(x, W1, h1, NNODES, GOUTD, FIN, GOUTD, nullptr, 0);
    attn_coef_kernel<<<NNODES / 8, 256>>>(h1, att_src1, att_dst1, asrc, adst);
    agg_kernel<<<NNODES, 256>>>(rowptr, srcarr, asrc, adst, h1, bias1, h2);

    // ===== GAT layer 2 =====
    launch_tgemm(h2, W2, h1, NNODES, GOUTD, GOUTD, GOUTD, nullptr, 0);
    attn_coef_kernel<<<NNODES / 8, 256>>>(h1, att_src2, att_dst2, asrc, adst);
    agg_kernel<<<NNODES, 256>>>(rowptr, srcarr, asrc, adst, h1, bias2, h2);

    // ===== global mean pool -> first half of concat buffer =====
    pool_kernel<<<NBATCH, 256>>>(h2, batch, cbuf);

    // ===== genomic encoder (writes second half of concat) =====
    launch_tgemm(x_gen, gW1, z1, NBATCH, 128, 735, 128, gb1, 3, bn_gamma, bn_beta, bn_mean, bn_var);
    launch_tgemm(z1, gW2, cbuf + 512, NBATCH, GOUTD, 128, 1024, gb2, 2);

    // ===== fusion MLP =====
    launch_tgemm(cbuf, fW1, f1, NBATCH, 256, 1024, 256, fb1, 2);
    launch_tgemm(f1, fW2, f2, NBATCH, 128, 256, 128, fb2, 2);
    final_dot_kernel<<<NBATCH, 32>>>(f2, fW3, fb3, out);
}